// round 3
// baseline (speedup 1.0000x reference)
#include <cuda_runtime.h>
#include <cstdint>

#define NN 100000
#define EE 1600000
#define DD 64
#define HH 256
#define OO 64

// -------- scratch (no allocs allowed) --------
__device__ int g_deg[NN];        // node degrees
__device__ int g_off[NN];        // exclusive offsets; after fill = segment END
__device__ int g_elist[EE];      // edge ids grouped by source node
__device__ int g_idx64;          // 1 if edge_index is int64, 0 if int32

// -------- helpers --------
__device__ __forceinline__ uint32_t f2tf_u(float x) {
    uint32_t u;
    asm("cvt.rna.tf32.f32 %0, %1;" : "=r"(u) : "f"(x));
    return u;
}
__device__ __forceinline__ float f2tf(float x) { return __uint_as_float(f2tf_u(x)); }

__device__ __forceinline__ void mma_tf32(float& d0, float& d1, float& d2, float& d3,
                                         uint32_t a0, uint32_t a1, uint32_t a2, uint32_t a3,
                                         uint32_t b0, uint32_t b1) {
    asm volatile(
        "mma.sync.aligned.m16n8k8.row.col.f32.tf32.tf32.f32 "
        "{%0,%1,%2,%3}, {%4,%5,%6,%7}, {%8,%9}, {%0,%1,%2,%3};"
        : "+f"(d0), "+f"(d1), "+f"(d2), "+f"(d3)
        : "r"(a0), "r"(a1), "r"(a2), "r"(a3), "r"(b0), "r"(b1));
}

// ============================================================
// Kernel 0: detect index dtype + zero degrees
// ============================================================
__global__ void init_kernel(const int* __restrict__ ei_words) {
    int t = blockIdx.x * blockDim.x + threadIdx.x;
    if (t == 0) {
        int acc = 0;
#pragma unroll
        for (int i = 1; i < 32; i += 2) acc |= ei_words[i];
        g_idx64 = (acc == 0) ? 1 : 0;
    }
    if (t < NN) g_deg[t] = 0;
}

// ============================================================
// Kernel 1: histogram of source rows
// ============================================================
__global__ void hist_kernel(const int* __restrict__ ei) {
    int e = blockIdx.x * blockDim.x + threadIdx.x;
    if (e >= EE) return;
    int row = g_idx64 ? ei[2 * e] : ei[e];
    if ((unsigned)row < (unsigned)NN) atomicAdd(&g_deg[row], 1);
}

// ============================================================
// Kernel 2: exclusive scan of degrees -> g_off (single block)
// ============================================================
__global__ void __launch_bounds__(1024, 1) scan_kernel() {
    __shared__ int ssum[1024];
    const int CHUNK = (NN + 1023) / 1024;   // 98
    int t = threadIdx.x;
    int start = t * CHUNK;
    int end = min(start + CHUNK, NN);
    int s = 0;
    for (int i = start; i < end; i++) s += g_deg[i];
    ssum[t] = s;
    __syncthreads();
    for (int o = 1; o < 1024; o <<= 1) {
        int v = (t >= o) ? ssum[t - o] : 0;
        __syncthreads();
        ssum[t] += v;
        __syncthreads();
    }
    int run = (t == 0) ? 0 : ssum[t - 1];
    for (int i = start; i < end; i++) {
        g_off[i] = run;
        run += g_deg[i];
    }
}

// ============================================================
// Kernel 3: fill edge list (g_off becomes segment END per node)
// ============================================================
__global__ void fill_kernel(const int* __restrict__ ei) {
    int e = blockIdx.x * blockDim.x + threadIdx.x;
    if (e >= EE) return;
    int row = g_idx64 ? ei[2 * e] : ei[e];
    if ((unsigned)row >= (unsigned)NN) return;
    int pos = atomicAdd(&g_off[row], 1);
    g_elist[pos] = e;
}

// ============================================================
// Kernel 4: fused gather + MLP
//   agg gathered per node from CSR; A = [x||agg]; out = relu(A@W1+b1)@W2+b2
//   TILE_M=64, 256 threads, 2 CTAs/SM for gather/mma overlap.
// smem "fragment permuted" layout: within every 8-col block, logical col j
// is at p(j) = ((j&3)<<1) | (j>>2)  -> A-fragment pair = contiguous lds.64.
// ============================================================
#define TILE_M    64
#define AS_STRIDE 136           // 128 + 8
#define HS_STRIDE 264           // 256 + 8
#define AW_FLOATS 8704          // max(64*136, W2 frag region 8192)
#define HS_FLOATS (TILE_M * HS_STRIDE)   // 16896
#define ELIST_CAP 2048
#define B1_OFF  (AW_FLOATS + HS_FLOATS)          // 25600
#define B2_OFF  (B1_OFF + HH)                    // 25856
#define ES_OFF  (B2_OFF + OO)                    // 25920
#define SMEM_FLOATS (ES_OFF + ELIST_CAP)         // 27968 -> 111872 B

__device__ __forceinline__ void storeA(float* A_s, int r, int c0, float4 v) {
    int blk = c0 >> 3;
    int bp  = (c0 & 4) ? 1 : 0;
    float* dst = A_s + r * AS_STRIDE + blk * 8;
    dst[bp + 0] = f2tf(v.x);
    dst[bp + 2] = f2tf(v.y);
    dst[bp + 4] = f2tf(v.z);
    dst[bp + 6] = f2tf(v.w);
}

__global__ void __launch_bounds__(256, 2)
mlp_kernel(const float* __restrict__ x, const float* __restrict__ ea,
           const float* __restrict__ W1g, const float* __restrict__ b1g,
           const float* __restrict__ W2g, const float* __restrict__ b2g,
           float* __restrict__ out) {
    extern __shared__ float smem[];
    float* A_s  = smem;          // reused for W2 fragments later
    float* W2f  = smem;
    float* h_s  = smem + AW_FLOATS;
    float* b1_s = smem + B1_OFF;
    float* b2_s = smem + B2_OFF;
    int*   es   = reinterpret_cast<int*>(smem + ES_OFF);

    const int tid  = threadIdx.x;
    const int warp = tid >> 5;
    const int lane = tid & 31;
    const int g    = lane >> 2;    // 0..7
    const int t4   = lane & 3;     // 0..3
    const int m_base = blockIdx.x * TILE_M;

    if (tid < HH) b1_s[tid] = b1g[tid];
    if (tid < OO) b2_s[tid] = b2g[tid];

    // ---- CTA edge-segment bounds (nodes are contiguous -> contiguous elist) ----
    int last = min(m_base + TILE_M - 1, NN - 1);
    int base = g_off[m_base] - g_deg[m_base];
    int cnt  = g_off[last] - base;
    int staged = min(cnt, ELIST_CAP);
    for (int i = tid; i < staged; i += 256) es[i] = g_elist[base + i];
    __syncthreads();

    // ---- Phase 0: gather agg + load x, write A tile [64 x 128] permuted ----
    {
        const int group = tid >> 4;     // 0..15
        const int l16   = tid & 15;     // float4 chunk 0..15
#pragma unroll
        for (int i = 0; i < 4; i++) {
            int r  = group * 4 + i;
            int gr = m_base + r;
            float4 acc = make_float4(0.f, 0.f, 0.f, 0.f);
            float4 xv  = make_float4(0.f, 0.f, 0.f, 0.f);
            if (gr < NN) {
                int dend   = g_off[gr];
                int dstart = dend - g_deg[gr];
                int ls = dstart - base, le = dend - base;
#pragma unroll 4
                for (int j = ls; j < le; j++) {
                    int e = (j < staged) ? es[j] : g_elist[base + j];
                    float4 v = __ldg(reinterpret_cast<const float4*>(ea) + (size_t)e * 16 + l16);
                    acc.x += v.x; acc.y += v.y; acc.z += v.z; acc.w += v.w;
                }
                xv = __ldg(reinterpret_cast<const float4*>(x) + (size_t)gr * 16 + l16);
            }
            storeA(A_s, r, l16 * 4, xv);
            storeA(A_s, r, 64 + l16 * 4, acc);
        }
    }
    __syncthreads();

    // perm positions for accumulator columns 2t and 2t+1
    const int p0 = (((2 * t4) & 3) << 1) | ((2 * t4) >> 2);
    const int p1 = (((2 * t4 + 1) & 3) << 1) | ((2 * t4 + 1) >> 2);

    // ---- Phase 1: GEMM1 h = relu(A @ W1 + b1), two 128-col halves ----
#pragma unroll
    for (int half = 0; half < 2; half++) {
        float acc[4][2][4];
#pragma unroll
        for (int mt = 0; mt < 4; mt++)
#pragma unroll
            for (int nt = 0; nt < 2; nt++)
#pragma unroll
                for (int i = 0; i < 4; i++) acc[mt][nt][i] = 0.f;

        const int n0 = half * 128 + warp * 16;
#pragma unroll
        for (int kk = 0; kk < 128; kk += 8) {
            const float* w1p = W1g + (size_t)(kk + t4) * HH + n0 + g;
            uint32_t b00 = f2tf_u(__ldg(w1p));
            uint32_t b01 = f2tf_u(__ldg(w1p + 4 * HH));
            uint32_t b10 = f2tf_u(__ldg(w1p + 8));
            uint32_t b11 = f2tf_u(__ldg(w1p + 4 * HH + 8));
#pragma unroll
            for (int mt = 0; mt < 4; mt++) {
                int r0 = mt * 16 + g;
                float2 a02 = *reinterpret_cast<const float2*>(A_s + r0 * AS_STRIDE + kk + 2 * t4);
                float2 a13 = *reinterpret_cast<const float2*>(A_s + (r0 + 8) * AS_STRIDE + kk + 2 * t4);
                uint32_t a0 = __float_as_uint(a02.x);
                uint32_t a1 = __float_as_uint(a13.x);
                uint32_t a2 = __float_as_uint(a02.y);
                uint32_t a3 = __float_as_uint(a13.y);
                mma_tf32(acc[mt][0][0], acc[mt][0][1], acc[mt][0][2], acc[mt][0][3],
                         a0, a1, a2, a3, b00, b01);
                mma_tf32(acc[mt][1][0], acc[mt][1][1], acc[mt][1][2], acc[mt][1][3],
                         a0, a1, a2, a3, b10, b11);
            }
        }
#pragma unroll
        for (int mt = 0; mt < 4; mt++) {
#pragma unroll
            for (int nt = 0; nt < 2; nt++) {
                int cbase = n0 + nt * 8;
                float bias0 = b1_s[cbase + 2 * t4];
                float bias1 = b1_s[cbase + 2 * t4 + 1];
                int r0 = mt * 16 + g;
                h_s[r0 * HS_STRIDE + cbase + p0]       = f2tf(fmaxf(acc[mt][nt][0] + bias0, 0.f));
                h_s[r0 * HS_STRIDE + cbase + p1]       = f2tf(fmaxf(acc[mt][nt][1] + bias1, 0.f));
                h_s[(r0 + 8) * HS_STRIDE + cbase + p0] = f2tf(fmaxf(acc[mt][nt][2] + bias0, 0.f));
                h_s[(r0 + 8) * HS_STRIDE + cbase + p1] = f2tf(fmaxf(acc[mt][nt][3] + bias1, 0.f));
            }
        }
    }
    __syncthreads();   // A_s free, h_s complete

    // ---- Phase 2: GEMM2 out = h @ W2 + b2, K staged in two halves ----
    const int mg = warp >> 1;   // m-tile 0..3
    const int ng = warp & 1;    // n half
    float acc2[4][4];
#pragma unroll
    for (int nt = 0; nt < 4; nt++)
#pragma unroll
        for (int i = 0; i < 4; i++) acc2[nt][i] = 0.f;

#pragma unroll
    for (int h2 = 0; h2 < 2; h2++) {
        // stage W2 rows [h2*128, h2*128+128) as fragment pairs:
        // W2f[(kb*64 + n)*8 + t4*2 + {0,1}] = W2[h2*128 + kb*8 + t4 (+4)][n]
#pragma unroll
        for (int idx = tid; idx < 4096; idx += 256) {
            int t4i = idx & 3;
            int n   = (idx >> 2) & 63;
            int kb  = idx >> 8;             // 0..15
            int krow = h2 * 128 + kb * 8 + t4i;
            float a = __ldg(W2g + (size_t)krow * OO + n);
            float b = __ldg(W2g + (size_t)(krow + 4) * OO + n);
            float* dst = W2f + (size_t)(kb * 64 + n) * 8 + t4i * 2;
            dst[0] = f2tf(a);
            dst[1] = f2tf(b);
        }
        __syncthreads();

#pragma unroll 4
        for (int kl = 0; kl < 128; kl += 8) {
            int kb = kl >> 3;
            int kk = h2 * 128 + kl;
            int r0 = mg * 16 + g;
            float2 a02 = *reinterpret_cast<const float2*>(h_s + r0 * HS_STRIDE + kk + 2 * t4);
            float2 a13 = *reinterpret_cast<const float2*>(h_s + (r0 + 8) * HS_STRIDE + kk + 2 * t4);
            uint32_t a0 = __float_as_uint(a02.x);
            uint32_t a1 = __float_as_uint(a13.x);
            uint32_t a2 = __float_as_uint(a02.y);
            uint32_t a3 = __float_as_uint(a13.y);
#pragma unroll
            for (int nt = 0; nt < 4; nt++) {
                int n = ng * 32 + nt * 8 + g;
                float2 bb = *reinterpret_cast<const float2*>(W2f + (size_t)(kb * 64 + n) * 8 + t4 * 2);
                mma_tf32(acc2[nt][0], acc2[nt][1], acc2[nt][2], acc2[nt][3],
                         __float_as_uint(a02.x), __float_as_uint(a13.x),
                         __float_as_uint(a02.y), __float_as_uint(a13.y),
                         __float_as_uint(bb.x), __float_as_uint(bb.y));
            }
            (void)a0; (void)a1; (void)a2; (void)a3;
        }
        __syncthreads();   // before restaging W2f
    }

    // epilogue: bias + store
#pragma unroll
    for (int nt = 0; nt < 4; nt++) {
        int col = ng * 32 + nt * 8 + 2 * t4;
        float bias0 = b2_s[col];
        float bias1 = b2_s[col + 1];
        int row = m_base + mg * 16 + g;
        if (row < NN)
            *reinterpret_cast<float2*>(out + (size_t)row * OO + col) =
                make_float2(acc2[nt][0] + bias0, acc2[nt][1] + bias1);
        if (row + 8 < NN)
            *reinterpret_cast<float2*>(out + (size_t)(row + 8) * OO + col) =
                make_float2(acc2[nt][2] + bias0, acc2[nt][3] + bias1);
    }
}

// ============================================================
extern "C" void kernel_launch(void* const* d_in, const int* in_sizes, int n_in,
                              void* d_out, int out_size) {
    const float* x   = (const float*)d_in[0];
    const int*   ei  = (const int*)d_in[1];   // int32 or int64 (auto-detected)
    const float* ea  = (const float*)d_in[2];
    // d_in[3] = u, d_in[4] = batch : unused
    const float* W1  = (const float*)d_in[5];
    const float* b1  = (const float*)d_in[6];
    const float* W2  = (const float*)d_in[7];
    const float* b2  = (const float*)d_in[8];
    float* out = (float*)d_out;

    init_kernel<<<(NN + 255) / 256, 256>>>(ei);
    hist_kernel<<<EE / 256, 256>>>(ei);
    scan_kernel<<<1, 1024>>>();
    fill_kernel<<<EE / 256, 256>>>(ei);

    size_t smem_bytes = SMEM_FLOATS * sizeof(float);   // 111872
    cudaFuncSetAttribute(mlp_kernel, cudaFuncAttributeMaxDynamicSharedMemorySize,
                         (int)smem_bytes);
    int mblocks = (NN + TILE_M - 1) / TILE_M;   // 1563
    mlp_kernel<<<mblocks, 256, smem_bytes>>>(x, ea, W1, b1, W2, b2, out);
}

// round 4
// speedup vs baseline: 1.0478x; 1.0478x over previous
#include <cuda_runtime.h>
#include <cstdint>

#define NN 100000
#define EE 1600000
#define DD 64
#define HH 256
#define OO 64

// -------- scratch (no allocs allowed) --------
__device__ float g_agg[(size_t)NN * DD];  // dense gathered sums
__device__ int g_deg[NN];                 // node degrees
__device__ int g_off[NN];                 // after fill: segment END per node
__device__ int g_elist[EE];               // edge ids grouped by source node
__device__ int g_idx64;                   // 1 if edge_index is int64, 0 if int32

// -------- helpers --------
__device__ __forceinline__ uint32_t f2tf_u(float x) {
    uint32_t u;
    asm("cvt.rna.tf32.f32 %0, %1;" : "=r"(u) : "f"(x));
    return u;
}
__device__ __forceinline__ float f2tf(float x) { return __uint_as_float(f2tf_u(x)); }

__device__ __forceinline__ void mma_tf32(float& d0, float& d1, float& d2, float& d3,
                                         uint32_t a0, uint32_t a1, uint32_t a2, uint32_t a3,
                                         uint32_t b0, uint32_t b1) {
    asm volatile(
        "mma.sync.aligned.m16n8k8.row.col.f32.tf32.tf32.f32 "
        "{%0,%1,%2,%3}, {%4,%5,%6,%7}, {%8,%9}, {%0,%1,%2,%3};"
        : "+f"(d0), "+f"(d1), "+f"(d2), "+f"(d3)
        : "r"(a0), "r"(a1), "r"(a2), "r"(a3), "r"(b0), "r"(b1));
}

// ============================================================
// Kernel 0: detect index dtype + zero degrees
// ============================================================
__global__ void init_kernel(const int* __restrict__ ei_words) {
    int t = blockIdx.x * blockDim.x + threadIdx.x;
    if (t == 0) {
        int acc = 0;
#pragma unroll
        for (int i = 1; i < 32; i += 2) acc |= ei_words[i];
        g_idx64 = (acc == 0) ? 1 : 0;
    }
    if (t < NN) g_deg[t] = 0;
}

// ============================================================
// Kernel 1: histogram of source rows
// ============================================================
__global__ void hist_kernel(const int* __restrict__ ei) {
    int e = blockIdx.x * blockDim.x + threadIdx.x;
    if (e >= EE) return;
    int row = g_idx64 ? __ldg(ei + 2 * e) : __ldg(ei + e);
    if ((unsigned)row < (unsigned)NN) atomicAdd(&g_deg[row], 1);
}

// ============================================================
// Kernel 2: exclusive scan of degrees -> g_off (single block)
// (validated in R3)
// ============================================================
__global__ void __launch_bounds__(1024, 1) scan_kernel() {
    __shared__ int ssum[1024];
    const int CHUNK = (NN + 1023) / 1024;   // 98
    int t = threadIdx.x;
    int start = t * CHUNK;
    int end = min(start + CHUNK, NN);
    int s = 0;
    for (int i = start; i < end; i++) s += g_deg[i];
    ssum[t] = s;
    __syncthreads();
    for (int o = 1; o < 1024; o <<= 1) {
        int v = (t >= o) ? ssum[t - o] : 0;
        __syncthreads();
        ssum[t] += v;
        __syncthreads();
    }
    int run = (t == 0) ? 0 : ssum[t - 1];
    for (int i = start; i < end; i++) {
        g_off[i] = run;
        run += g_deg[i];
    }
}

// ============================================================
// Kernel 3: fill edge list (g_off becomes segment END per node)
// ============================================================
__global__ void fill_kernel(const int* __restrict__ ei) {
    int e = blockIdx.x * blockDim.x + threadIdx.x;
    if (e >= EE) return;
    int row = g_idx64 ? __ldg(ei + 2 * e) : __ldg(ei + e);
    if ((unsigned)row >= (unsigned)NN) return;
    int pos = atomicAdd(&g_off[row], 1);
    g_elist[pos] = e;
}

// ============================================================
// Kernel 4: warp-per-node gather (atomic-free segment sum)
// 2 edges in parallel per warp (16 threads x float4 each), then
// a cross-half shuffle reduction; coalesced 256B row write.
// ============================================================
__global__ void gather_kernel(const float* __restrict__ ea) {
    int w = (blockIdx.x * blockDim.x + threadIdx.x) >> 5;
    if (w >= NN) return;
    int lane = threadIdx.x & 31;
    int esel = lane >> 4;      // which of 2 parallel edges
    int l16  = lane & 15;      // float4 chunk within row

    int end   = g_off[w];
    int start = end - g_deg[w];
    float4 acc = make_float4(0.f, 0.f, 0.f, 0.f);
#pragma unroll 4
    for (int j = start + esel; j < end; j += 2) {
        int e = __ldg(g_elist + j);
        float4 v = __ldg(reinterpret_cast<const float4*>(ea) + (size_t)e * 16 + l16);
        acc.x += v.x; acc.y += v.y; acc.z += v.z; acc.w += v.w;
    }
    acc.x += __shfl_xor_sync(0xffffffffu, acc.x, 16);
    acc.y += __shfl_xor_sync(0xffffffffu, acc.y, 16);
    acc.z += __shfl_xor_sync(0xffffffffu, acc.z, 16);
    acc.w += __shfl_xor_sync(0xffffffffu, acc.w, 16);
    if (lane < 16)
        reinterpret_cast<float4*>(g_agg)[(size_t)w * 16 + l16] = acc;
}

// ============================================================
// Kernel 5: fused MLP  out = relu([x||agg] @ W1 + b1) @ W2 + b2
// (byte-for-byte the validated R2 kernel)
// ============================================================
#define TILE_M    128
#define AS_STRIDE 136          // 128 + 8
#define HS_STRIDE 264          // 256 + 8
#define W2_STRIDE 72           // 64 + 8
#define AS_FLOATS (256 * W2_STRIDE)     // 18432
#define HS_FLOATS (TILE_M * HS_STRIDE)  // 33792
#define SMEM_FLOATS (AS_FLOATS + HS_FLOATS + HH + OO)  // 52544 -> 210176 B

__global__ void __launch_bounds__(256, 1)
mlp_kernel(const float* __restrict__ x,
           const float* __restrict__ W1g, const float* __restrict__ b1g,
           const float* __restrict__ W2g, const float* __restrict__ b2g,
           float* __restrict__ out) {
    extern __shared__ float smem[];
    float* A_s  = smem;
    float* W2_s = smem;
    float* h_s  = smem + AS_FLOATS;
    float* b1_s = smem + AS_FLOATS + HS_FLOATS;
    float* b2_s = b1_s + HH;

    const int tid  = threadIdx.x;
    const int warp = tid >> 5;
    const int lane = tid & 31;
    const int g    = lane >> 2;
    const int t4   = lane & 3;
    const int m_base = blockIdx.x * TILE_M;

    if (tid < HH) b1_s[tid] = b1g[tid];
    if (tid < OO) b2_s[tid] = b2g[tid];

    // ---- Phase 0: load A tile [128 x 128] = [x | agg], tf32-rounded, permuted ----
#pragma unroll
    for (int i = 0; i < 16; i++) {
        int idx = tid + i * 256;
        int r = idx >> 5;
        int q = idx & 31;
        int gr = m_base + r;
        float4 v;
        if (gr < NN) {
            if (q < 16) v = __ldg(reinterpret_cast<const float4*>(x) + (size_t)gr * 16 + q);
            else        v = *(reinterpret_cast<const float4*>(g_agg) + (size_t)gr * 16 + (q - 16));
        } else {
            v = make_float4(0.f, 0.f, 0.f, 0.f);
        }
        int c0  = q * 4;
        int blk = c0 >> 3;
        int bp  = (c0 & 4) ? 1 : 0;
        float* dst = A_s + r * AS_STRIDE + blk * 8;
        dst[bp + 0] = f2tf(v.x);
        dst[bp + 2] = f2tf(v.y);
        dst[bp + 4] = f2tf(v.z);
        dst[bp + 6] = f2tf(v.w);
    }
    __syncthreads();

    const int p0 = (((2 * t4) & 3) << 1) | ((2 * t4) >> 2);
    const int p1 = (((2 * t4 + 1) & 3) << 1) | ((2 * t4 + 1) >> 2);

    // ---- Phase 1: GEMM1 h = relu(A @ W1 + b1), two 128-col halves ----
#pragma unroll
    for (int half = 0; half < 2; half++) {
        float acc[8][2][4];
#pragma unroll
        for (int mt = 0; mt < 8; mt++)
#pragma unroll
            for (int nt = 0; nt < 2; nt++)
#pragma unroll
                for (int i = 0; i < 4; i++) acc[mt][nt][i] = 0.f;

        const int n0 = half * 128 + warp * 16;
#pragma unroll
        for (int kk = 0; kk < 128; kk += 8) {
            const float* w1p = W1g + (size_t)(kk + t4) * HH + n0 + g;
            uint32_t b00 = f2tf_u(__ldg(w1p));
            uint32_t b01 = f2tf_u(__ldg(w1p + 4 * HH));
            uint32_t b10 = f2tf_u(__ldg(w1p + 8));
            uint32_t b11 = f2tf_u(__ldg(w1p + 4 * HH + 8));
#pragma unroll
            for (int mt = 0; mt < 8; mt++) {
                int r0 = mt * 16 + g;
                float2 a02 = *reinterpret_cast<const float2*>(A_s + r0 * AS_STRIDE + kk + 2 * t4);
                float2 a13 = *reinterpret_cast<const float2*>(A_s + (r0 + 8) * AS_STRIDE + kk + 2 * t4);
                uint32_t a0 = __float_as_uint(a02.x);
                uint32_t a1 = __float_as_uint(a13.x);
                uint32_t a2 = __float_as_uint(a02.y);
                uint32_t a3 = __float_as_uint(a13.y);
                mma_tf32(acc[mt][0][0], acc[mt][0][1], acc[mt][0][2], acc[mt][0][3],
                         a0, a1, a2, a3, b00, b01);
                mma_tf32(acc[mt][1][0], acc[mt][1][1], acc[mt][1][2], acc[mt][1][3],
                         a0, a1, a2, a3, b10, b11);
            }
        }
#pragma unroll
        for (int mt = 0; mt < 8; mt++) {
#pragma unroll
            for (int nt = 0; nt < 2; nt++) {
                int cbase = n0 + nt * 8;
                float bias0 = b1_s[cbase + 2 * t4];
                float bias1 = b1_s[cbase + 2 * t4 + 1];
                int r0 = mt * 16 + g;
                h_s[r0 * HS_STRIDE + cbase + p0]       = f2tf(fmaxf(acc[mt][nt][0] + bias0, 0.f));
                h_s[r0 * HS_STRIDE + cbase + p1]       = f2tf(fmaxf(acc[mt][nt][1] + bias1, 0.f));
                h_s[(r0 + 8) * HS_STRIDE + cbase + p0] = f2tf(fmaxf(acc[mt][nt][2] + bias0, 0.f));
                h_s[(r0 + 8) * HS_STRIDE + cbase + p1] = f2tf(fmaxf(acc[mt][nt][3] + bias1, 0.f));
            }
        }
    }
    __syncthreads();

    // ---- stage W2 [256 x 64] into freed A_s region ----
#pragma unroll
    for (int i = 0; i < 16; i++) {
        int idx = tid + i * 256;
        int r = idx >> 4;
        int q = idx & 15;
        float4 v = __ldg(reinterpret_cast<const float4*>(W2g) + (size_t)r * 16 + q);
        float* dst = W2_s + r * W2_STRIDE + q * 4;
        dst[0] = f2tf(v.x); dst[1] = f2tf(v.y); dst[2] = f2tf(v.z); dst[3] = f2tf(v.w);
    }
    __syncthreads();

    // ---- Phase 2: GEMM2 out = h @ W2 + b2 ----
    const int mg = warp >> 1;
    const int ng = warp & 1;
    float acc2[2][4][4];
#pragma unroll
    for (int mt = 0; mt < 2; mt++)
#pragma unroll
        for (int nt = 0; nt < 4; nt++)
#pragma unroll
            for (int i = 0; i < 4; i++) acc2[mt][nt][i] = 0.f;

#pragma unroll 8
    for (int kk = 0; kk < 256; kk += 8) {
        uint32_t bb[4][2];
#pragma unroll
        for (int nt = 0; nt < 4; nt++) {
            int n = ng * 32 + nt * 8 + g;
            bb[nt][0] = __float_as_uint(W2_s[(kk + t4) * W2_STRIDE + n]);
            bb[nt][1] = __float_as_uint(W2_s[(kk + t4 + 4) * W2_STRIDE + n]);
        }
#pragma unroll
        for (int mt = 0; mt < 2; mt++) {
            int r0 = (mg * 2 + mt) * 16 + g;
            float2 a02 = *reinterpret_cast<const float2*>(h_s + r0 * HS_STRIDE + kk + 2 * t4);
            float2 a13 = *reinterpret_cast<const float2*>(h_s + (r0 + 8) * HS_STRIDE + kk + 2 * t4);
            uint32_t a0 = __float_as_uint(a02.x);
            uint32_t a1 = __float_as_uint(a13.x);
            uint32_t a2 = __float_as_uint(a02.y);
            uint32_t a3 = __float_as_uint(a13.y);
#pragma unroll
            for (int nt = 0; nt < 4; nt++)
                mma_tf32(acc2[mt][nt][0], acc2[mt][nt][1], acc2[mt][nt][2], acc2[mt][nt][3],
                         a0, a1, a2, a3, bb[nt][0], bb[nt][1]);
        }
    }

#pragma unroll
    for (int mt = 0; mt < 2; mt++) {
#pragma unroll
        for (int nt = 0; nt < 4; nt++) {
            int col = ng * 32 + nt * 8 + 2 * t4;
            float bias0 = b2_s[col];
            float bias1 = b2_s[col + 1];
            int row = m_base + (mg * 2 + mt) * 16 + g;
            if (row < NN)
                *reinterpret_cast<float2*>(out + (size_t)row * OO + col) =
                    make_float2(acc2[mt][nt][0] + bias0, acc2[mt][nt][1] + bias1);
            if (row + 8 < NN)
                *reinterpret_cast<float2*>(out + (size_t)(row + 8) * OO + col) =
                    make_float2(acc2[mt][nt][2] + bias0, acc2[mt][nt][3] + bias1);
        }
    }
}

// ============================================================
extern "C" void kernel_launch(void* const* d_in, const int* in_sizes, int n_in,
                              void* d_out, int out_size) {
    const float* x   = (const float*)d_in[0];
    const int*   ei  = (const int*)d_in[1];   // int32 or int64 (auto-detected)
    const float* ea  = (const float*)d_in[2];
    // d_in[3] = u, d_in[4] = batch : unused
    const float* W1  = (const float*)d_in[5];
    const float* b1  = (const float*)d_in[6];
    const float* W2  = (const float*)d_in[7];
    const float* b2  = (const float*)d_in[8];
    float* out = (float*)d_out;

    init_kernel<<<(NN + 255) / 256, 256>>>(ei);
    hist_kernel<<<EE / 256, 256>>>(ei);
    scan_kernel<<<1, 1024>>>();
    fill_kernel<<<EE / 256, 256>>>(ei);
    gather_kernel<<<(NN * 32 + 255) / 256, 256>>>(ea);   // 12500 blocks

    size_t smem_bytes = SMEM_FLOATS * sizeof(float);     // 210176
    cudaFuncSetAttribute(mlp_kernel, cudaFuncAttributeMaxDynamicSharedMemorySize,
                         (int)smem_bytes);
    int mblocks = (NN + TILE_M - 1) / TILE_M;            // 782
    mlp_kernel<<<mblocks, 256, smem_bytes>>>(x, W1, b1, W2, b2, out);
}